// round 4
// baseline (speedup 1.0000x reference)
#include <cuda_runtime.h>
#include <cuda_bf16.h>
#include <math.h>
#include <stdint.h>

#define N_NODES_C 100000
#define N_EDGES_C 600000
#define D_C       128
#define TPB       256
#define TILE_M    128
#define GEMM_GRID ((N_NODES_C + TILE_M - 1) / TILE_M)   // 782

#define RS        136                      // smem row stride in bf16 (272B, conflict-free ldmatrix)
#define TILE_HALF (TILE_M * RS)
#define TILE_BYTES_SM (TILE_HALF * 2)      // 34816 B

#define SCAN_B    1024
#define NB_SCAN   ((N_NODES_C + SCAN_B - 1) / SCAN_B)   // 98

// -------- device scratch (static; no allocation allowed) --------
__device__ int g_deg[N_NODES_C];
__device__ int g_incl[N_NODES_C];
__device__ int g_bsum[128];
__device__ int g_off[N_NODES_C + 1];
__device__ int g_cursor[N_NODES_C];
__device__ int g_esrc[N_EDGES_C];

__device__ __forceinline__ uint32_t smem_u32(const void* p) {
    uint32_t a;
    asm("{ .reg .u64 t; cvta.to.shared.u64 t, %1; cvt.u32.u64 %0, t; }" : "=r"(a) : "l"(p));
    return a;
}

// ---------------------------------------------------------------------------
// K1: zero degree counters
// ---------------------------------------------------------------------------
__global__ void zero_deg_kernel() {
    int i = blockIdx.x * blockDim.x + threadIdx.x;
    if (i < N_NODES_C) g_deg[i] = 0;
}

// ---------------------------------------------------------------------------
// K2: histogram of dst
// ---------------------------------------------------------------------------
__global__ void hist_kernel(const int* __restrict__ dst, int n_edges) {
    int e = blockIdx.x * blockDim.x + threadIdx.x;
    if (e < n_edges) atomicAdd(&g_deg[dst[e]], 1);
}

// ---------------------------------------------------------------------------
// K3: per-1024-block inclusive scan of deg -> g_incl, block sums -> g_bsum
// ---------------------------------------------------------------------------
__global__ __launch_bounds__(SCAN_B) void scan_a_kernel() {
    __shared__ int ss[SCAN_B];
    int tid = threadIdx.x;
    int n   = blockIdx.x * SCAN_B + tid;
    int v   = (n < N_NODES_C) ? g_deg[n] : 0;
    ss[tid] = v;
    __syncthreads();
    #pragma unroll
    for (int off = 1; off < SCAN_B; off <<= 1) {
        int t = (tid >= off) ? ss[tid - off] : 0;
        __syncthreads();
        ss[tid] += t;
        __syncthreads();
    }
    if (n < N_NODES_C) g_incl[n] = ss[tid];
    if (tid == SCAN_B - 1) g_bsum[blockIdx.x] = ss[tid];
}

// ---------------------------------------------------------------------------
// K4: finalize offsets: excl = incl - deg + prefix(block sums); also cursor
// ---------------------------------------------------------------------------
__global__ __launch_bounds__(SCAN_B) void scan_c_kernel(int n_edges) {
    __shared__ int partial[4];
    int tid = threadIdx.x, bid = blockIdx.x;
    if (tid < 128) {
        int v = (tid < bid && tid < NB_SCAN) ? g_bsum[tid] : 0;
        #pragma unroll
        for (int o = 16; o > 0; o >>= 1) v += __shfl_down_sync(0xffffffffu, v, o);
        if ((tid & 31) == 0) partial[tid >> 5] = v;
    }
    __syncthreads();
    int bpre = partial[0] + partial[1] + partial[2] + partial[3];
    int n = bid * SCAN_B + tid;
    if (n < N_NODES_C) {
        int excl = g_incl[n] - g_deg[n] + bpre;
        g_off[n]    = excl;
        g_cursor[n] = excl;
    }
    if (bid == 0 && tid == 0) g_off[N_NODES_C] = n_edges;
}

// ---------------------------------------------------------------------------
// K5: permute edges into CSR-by-dst order (store src ids)
// ---------------------------------------------------------------------------
__global__ void permute_kernel(const int* __restrict__ src,
                               const int* __restrict__ dst, int n_edges) {
    int e = blockIdx.x * blockDim.x + threadIdx.x;
    if (e < n_edges) {
        int d   = dst[e];
        int pos = atomicAdd(&g_cursor[d], 1);
        g_esrc[pos] = src[e];
    }
}

// ---------------------------------------------------------------------------
// K6: fused gather + residual + norm + bf16-split HMMA GEMM
// ---------------------------------------------------------------------------
__device__ __forceinline__ void ldsm_x4(uint32_t addr, uint32_t& r0, uint32_t& r1,
                                        uint32_t& r2, uint32_t& r3) {
    asm volatile("ldmatrix.sync.aligned.m8n8.x4.shared.b16 {%0,%1,%2,%3}, [%4];"
                 : "=r"(r0), "=r"(r1), "=r"(r2), "=r"(r3) : "r"(addr));
}
__device__ __forceinline__ void mma16816(float& c0, float& c1, float& c2, float& c3,
                                         uint32_t a0, uint32_t a1, uint32_t a2, uint32_t a3,
                                         uint32_t b0, uint32_t b1) {
    asm volatile("mma.sync.aligned.m16n8k16.row.col.f32.bf16.bf16.f32 "
                 "{%0,%1,%2,%3}, {%4,%5,%6,%7}, {%8,%9}, {%0,%1,%2,%3};"
                 : "+f"(c0), "+f"(c1), "+f"(c2), "+f"(c3)
                 : "r"(a0), "r"(a1), "r"(a2), "r"(a3), "r"(b0), "r"(b1));
}
__device__ __forceinline__ void split2(float v0, float v1, uint32_t& hi, uint32_t& lo) {
    __nv_bfloat162 h2 = __floats2bfloat162_rn(v0, v1);
    float r0 = v0 - __bfloat162float(h2.x);
    float r1 = v1 - __bfloat162float(h2.y);
    __nv_bfloat162 l2 = __floats2bfloat162_rn(r0, r1);
    hi = *(uint32_t*)&h2;
    lo = *(uint32_t*)&l2;
}

__global__ __launch_bounds__(TPB, 1) void gemm_kernel(const float* __restrict__ feat,
                                                      const float* __restrict__ W,
                                                      const float* __restrict__ b,
                                                      float* __restrict__ out) {
    extern __shared__ __align__(16) __nv_bfloat16 sm[];
    __nv_bfloat16* Ahi = sm;
    __nv_bfloat16* Alo = Ahi + TILE_HALF;
    __nv_bfloat16* Bhi = Alo + TILE_HALF;
    __nv_bfloat16* Blo = Bhi + TILE_HALF;
    __shared__ float bs[D_C];

    const int tid  = threadIdx.x;
    const int wid  = tid >> 5;
    const int lane = tid & 31;
    const int base = blockIdx.x * TILE_M;

    if (tid < D_C) bs[tid] = b[tid];

    // ---- B tile: split W into bf16 hi/lo (2048 groups of 8 floats) ----
    #pragma unroll
    for (int it = 0; it < 8; ++it) {
        int idx = tid + it * TPB;
        int row = idx >> 4;
        int kc  = (idx & 15) << 3;
        int so  = row * RS + kc;
        const float4* wp = (const float4*)(W + (size_t)row * D_C + kc);
        float4 w0 = wp[0], w1 = wp[1];
        float v[8] = {w0.x, w0.y, w0.z, w0.w, w1.x, w1.y, w1.z, w1.w};
        uint32_t hi[4], lo[4];
        #pragma unroll
        for (int j = 0; j < 4; j++) split2(v[2*j], v[2*j+1], hi[j], lo[j]);
        *(uint4*)(Bhi + so) = make_uint4(hi[0], hi[1], hi[2], hi[3]);
        *(uint4*)(Blo + so) = make_uint4(lo[0], lo[1], lo[2], lo[3]);
    }

    // ---- A tile: CSR gather + residual + norm, split to bf16 hi/lo ----
    // Warp w owns nodes [w*16, w*16+16); each lane holds one float4 of the row.
    for (int i = 0; i < 16; ++i) {
        int m    = wid * 16 + i;
        int node = base + m;
        float4 a0 = make_float4(0.f, 0.f, 0.f, 0.f);
        if (node < N_NODES_C) {
            a0 = ((const float4*)(feat + (size_t)node * D_C))[lane];   // residual
            int e0 = g_off[node];
            int e1 = g_off[node + 1];
            float4 a1 = make_float4(0.f, 0.f, 0.f, 0.f);
            float4 a2 = make_float4(0.f, 0.f, 0.f, 0.f);
            float4 a3 = make_float4(0.f, 0.f, 0.f, 0.f);
            int e = e0;
            for (; e + 4 <= e1; e += 4) {
                int s0 = __ldg(g_esrc + e + 0);
                int s1 = __ldg(g_esrc + e + 1);
                int s2 = __ldg(g_esrc + e + 2);
                int s3 = __ldg(g_esrc + e + 3);
                float4 v0 = ((const float4*)(feat + (size_t)s0 * D_C))[lane];
                float4 v1 = ((const float4*)(feat + (size_t)s1 * D_C))[lane];
                float4 v2 = ((const float4*)(feat + (size_t)s2 * D_C))[lane];
                float4 v3 = ((const float4*)(feat + (size_t)s3 * D_C))[lane];
                a0.x += v0.x; a0.y += v0.y; a0.z += v0.z; a0.w += v0.w;
                a1.x += v1.x; a1.y += v1.y; a1.z += v1.z; a1.w += v1.w;
                a2.x += v2.x; a2.y += v2.y; a2.z += v2.z; a2.w += v2.w;
                a3.x += v3.x; a3.y += v3.y; a3.z += v3.z; a3.w += v3.w;
            }
            for (; e < e1; ++e) {
                int s0 = __ldg(g_esrc + e);
                float4 v0 = ((const float4*)(feat + (size_t)s0 * D_C))[lane];
                a0.x += v0.x; a0.y += v0.y; a0.z += v0.z; a0.w += v0.w;
            }
            a0.x += a1.x + a2.x + a3.x;
            a0.y += a1.y + a2.y + a3.y;
            a0.z += a1.z + a2.z + a3.z;
            a0.w += a1.w + a2.w + a3.w;
            float nrm = rsqrtf(fmaxf((float)(e1 - e0), 1.0f));
            a0.x *= nrm; a0.y *= nrm; a0.z *= nrm; a0.w *= nrm;
        }
        uint32_t h0, h1, l0, l1;
        split2(a0.x, a0.y, h0, l0);
        split2(a0.z, a0.w, h1, l1);
        int so = m * RS + lane * 4;
        *(uint2*)(Ahi + so) = make_uint2(h0, h1);
        *(uint2*)(Alo + so) = make_uint2(l0, l1);
    }
    __syncthreads();

    // ---- HMMA mainloop (identical to R3): 4(M) x 2(N) warp tiling ----
    const int m0 = (wid & 3) * 32;
    const int n0 = (wid >> 2) * 64;

    float acc[2][8][4];
    #pragma unroll
    for (int f = 0; f < 2; f++)
        #pragma unroll
        for (int nb = 0; nb < 8; nb++)
            #pragma unroll
            for (int j = 0; j < 4; j++) acc[f][nb][j] = 0.f;

    uint32_t aBase[2];
    #pragma unroll
    for (int f = 0; f < 2; f++)
        aBase[f] = smem_u32(Ahi) +
                   (uint32_t)(((m0 + f * 16 + (lane & 15)) * RS + ((lane >> 4) << 3)) * 2);
    uint32_t bBase[4];
    #pragma unroll
    for (int p = 0; p < 4; p++)
        bBase[p] = smem_u32(Bhi) +
                   (uint32_t)(((n0 + 16 * p + (lane & 7) + ((lane >> 4) << 3)) * RS +
                               (((lane >> 3) & 1) << 3)) * 2);

    const uint32_t LO_D = (uint32_t)TILE_BYTES_SM;

    #pragma unroll
    for (int prod = 0; prod < 3; prod++) {
        uint32_t dA = (prod == 1) ? LO_D : 0u;
        uint32_t dB = (prod == 2) ? LO_D : 0u;
        #pragma unroll
        for (int kk = 0; kk < 8; kk++) {
            uint32_t koff = (uint32_t)(kk * 16 * 2);
            uint32_t a[2][4];
            #pragma unroll
            for (int f = 0; f < 2; f++)
                ldsm_x4(aBase[f] + dA + koff, a[f][0], a[f][1], a[f][2], a[f][3]);
            #pragma unroll
            for (int p = 0; p < 4; p++) {
                uint32_t b0, b1, b2, b3;
                ldsm_x4(bBase[p] + dB + koff, b0, b1, b2, b3);
                #pragma unroll
                for (int f = 0; f < 2; f++) {
                    mma16816(acc[f][2*p  ][0], acc[f][2*p  ][1], acc[f][2*p  ][2], acc[f][2*p  ][3],
                             a[f][0], a[f][1], a[f][2], a[f][3], b0, b1);
                    mma16816(acc[f][2*p+1][0], acc[f][2*p+1][1], acc[f][2*p+1][2], acc[f][2*p+1][3],
                             a[f][0], a[f][1], a[f][2], a[f][3], b2, b3);
                }
            }
        }
    }

    // ---- epilogue ----
    const int qr = lane >> 2;
    const int qc = (lane & 3) * 2;
    #pragma unroll
    for (int f = 0; f < 2; f++) {
        int m_lo = m0 + f * 16 + qr;
        int m_hi = m_lo + 8;
        int node_lo = base + m_lo;
        int node_hi = base + m_hi;
        #pragma unroll
        for (int nb = 0; nb < 8; nb++) {
            int col = n0 + nb * 8 + qc;
            float b0v = bs[col], b1v = bs[col + 1];
            if (node_lo < N_NODES_C) {
                float2 o = make_float2(acc[f][nb][0] + b0v, acc[f][nb][1] + b1v);
                *(float2*)(out + (size_t)node_lo * D_C + col) = o;
            }
            if (node_hi < N_NODES_C) {
                float2 o = make_float2(acc[f][nb][2] + b0v, acc[f][nb][3] + b1v);
                *(float2*)(out + (size_t)node_hi * D_C + col) = o;
            }
        }
    }
}

// ---------------------------------------------------------------------------
// kernel_launch
// ---------------------------------------------------------------------------
extern "C" void kernel_launch(void* const* d_in, const int* in_sizes, int n_in,
                              void* d_out, int out_size) {
    const float* feat = (const float*)d_in[0];   // [100000,128] f32
    const int*   src  = (const int*)d_in[1];     // [600000] i32
    const int*   dst  = (const int*)d_in[2];     // [600000] i32
    const float* W    = (const float*)d_in[3];   // [128,128] f32
    const float* b    = (const float*)d_in[4];   // [128] f32
    float*       out  = (float*)d_out;

    const int n_edges = in_sizes[1];

    const int smem_bytes = 4 * TILE_BYTES_SM;    // 139264 B dynamic
    cudaFuncSetAttribute(gemm_kernel,
                         cudaFuncAttributeMaxDynamicSharedMemorySize, smem_bytes);

    // CSR build
    zero_deg_kernel<<<(N_NODES_C + TPB - 1) / TPB, TPB>>>();
    hist_kernel<<<(n_edges + TPB - 1) / TPB, TPB>>>(dst, n_edges);
    scan_a_kernel<<<NB_SCAN, SCAN_B>>>();
    scan_c_kernel<<<NB_SCAN, SCAN_B>>>(n_edges);
    permute_kernel<<<(n_edges + TPB - 1) / TPB, TPB>>>(src, dst, n_edges);

    // fused gather + norm + HMMA GEMM
    gemm_kernel<<<GEMM_GRID, TPB, smem_bytes>>>(feat, W, b, out);
}

// round 5
// speedup vs baseline: 1.4583x; 1.4583x over previous
#include <cuda_runtime.h>
#include <cuda_bf16.h>
#include <math.h>
#include <stdint.h>

#define N_NODES_C 100000
#define N_EDGES_C 600000
#define D_C       128
#define TPB       256
#define TILE_M    128
#define GEMM_GRID ((N_NODES_C + TILE_M - 1) / TILE_M)   // 782

#define RS        136                      // smem row stride in bf16 (272B, conflict-free ldmatrix)
#define TILE_HALF (TILE_M * RS)
#define TILE_BYTES_SM (TILE_HALF * 2)      // 34816 B

#define SCAN_B    1024
#define NB_SCAN   ((N_NODES_C + SCAN_B - 1) / SCAN_B)   // 98

// -------- device scratch (static; no allocation allowed) --------
__device__ int g_deg[N_NODES_C];
__device__ int g_incl[N_NODES_C];
__device__ int g_bsum[128];
__device__ int g_off[N_NODES_C + 1];
__device__ int g_cursor[N_NODES_C];
__device__ int g_esrc[N_EDGES_C];
// h pre-split to bf16: per node 64 uint32 words (hi) + 64 (lo); 25.6 MB each
__device__ uint32_t g_hi[(size_t)N_NODES_C * 64];
__device__ uint32_t g_lo[(size_t)N_NODES_C * 64];

__device__ __forceinline__ uint32_t smem_u32(const void* p) {
    uint32_t a;
    asm("{ .reg .u64 t; cvta.to.shared.u64 t, %1; cvt.u32.u64 %0, t; }" : "=r"(a) : "l"(p));
    return a;
}

__device__ __forceinline__ void split2(float v0, float v1, uint32_t& hi, uint32_t& lo) {
    __nv_bfloat162 h2 = __floats2bfloat162_rn(v0, v1);
    float r0 = v0 - __bfloat162float(h2.x);
    float r1 = v1 - __bfloat162float(h2.y);
    __nv_bfloat162 l2 = __floats2bfloat162_rn(r0, r1);
    hi = *(uint32_t*)&h2;
    lo = *(uint32_t*)&l2;
}

// ---------------------------------------------------------------------------
// K1: zero degree counters
// ---------------------------------------------------------------------------
__global__ void zero_deg_kernel() {
    int i = blockIdx.x * blockDim.x + threadIdx.x;
    if (i < N_NODES_C) g_deg[i] = 0;
}

// ---------------------------------------------------------------------------
// K2: histogram of dst
// ---------------------------------------------------------------------------
__global__ void hist_kernel(const int* __restrict__ dst, int n_edges) {
    int e = blockIdx.x * blockDim.x + threadIdx.x;
    if (e < n_edges) atomicAdd(&g_deg[dst[e]], 1);
}

// ---------------------------------------------------------------------------
// K3: per-1024-block inclusive scan of deg
// ---------------------------------------------------------------------------
__global__ __launch_bounds__(SCAN_B) void scan_a_kernel() {
    __shared__ int ss[SCAN_B];
    int tid = threadIdx.x;
    int n   = blockIdx.x * SCAN_B + tid;
    int v   = (n < N_NODES_C) ? g_deg[n] : 0;
    ss[tid] = v;
    __syncthreads();
    #pragma unroll
    for (int off = 1; off < SCAN_B; off <<= 1) {
        int t = (tid >= off) ? ss[tid - off] : 0;
        __syncthreads();
        ss[tid] += t;
        __syncthreads();
    }
    if (n < N_NODES_C) g_incl[n] = ss[tid];
    if (tid == SCAN_B - 1) g_bsum[blockIdx.x] = ss[tid];
}

// ---------------------------------------------------------------------------
// K4: finalize offsets
// ---------------------------------------------------------------------------
__global__ __launch_bounds__(SCAN_B) void scan_c_kernel(int n_edges) {
    __shared__ int partial[4];
    int tid = threadIdx.x, bid = blockIdx.x;
    if (tid < 128) {
        int v = (tid < bid && tid < NB_SCAN) ? g_bsum[tid] : 0;
        #pragma unroll
        for (int o = 16; o > 0; o >>= 1) v += __shfl_down_sync(0xffffffffu, v, o);
        if ((tid & 31) == 0) partial[tid >> 5] = v;
    }
    __syncthreads();
    int bpre = partial[0] + partial[1] + partial[2] + partial[3];
    int n = bid * SCAN_B + tid;
    if (n < N_NODES_C) {
        int excl = g_incl[n] - g_deg[n] + bpre;
        g_off[n]    = excl;
        g_cursor[n] = excl;
    }
    if (bid == 0 && tid == 0) g_off[N_NODES_C] = n_edges;
}

// ---------------------------------------------------------------------------
// K5: permute edges into CSR-by-dst order
// ---------------------------------------------------------------------------
__global__ void permute_kernel(const int* __restrict__ src,
                               const int* __restrict__ dst, int n_edges) {
    int e = blockIdx.x * blockDim.x + threadIdx.x;
    if (e < n_edges) {
        int d   = dst[e];
        int pos = atomicAdd(&g_cursor[d], 1);
        g_esrc[pos] = src[e];
    }
}

// ---------------------------------------------------------------------------
// K6: gather + residual + norm + bf16 split  (warp per node, no smem)
// ---------------------------------------------------------------------------
__global__ __launch_bounds__(TPB) void gather_kernel(const float* __restrict__ feat) {
    int node = (blockIdx.x * blockDim.x + threadIdx.x) >> 5;
    int lane = threadIdx.x & 31;
    if (node >= N_NODES_C) return;

    float4 a0 = ((const float4*)(feat + (size_t)node * D_C))[lane];   // residual
    int e0 = g_off[node];
    int e1 = g_off[node + 1];

    float4 a1 = make_float4(0.f, 0.f, 0.f, 0.f);
    float4 a2 = make_float4(0.f, 0.f, 0.f, 0.f);
    float4 a3 = make_float4(0.f, 0.f, 0.f, 0.f);
    int e = e0;
    for (; e + 4 <= e1; e += 4) {
        int s0 = __ldg(g_esrc + e + 0);
        int s1 = __ldg(g_esrc + e + 1);
        int s2 = __ldg(g_esrc + e + 2);
        int s3 = __ldg(g_esrc + e + 3);
        float4 v0 = ((const float4*)(feat + (size_t)s0 * D_C))[lane];
        float4 v1 = ((const float4*)(feat + (size_t)s1 * D_C))[lane];
        float4 v2 = ((const float4*)(feat + (size_t)s2 * D_C))[lane];
        float4 v3 = ((const float4*)(feat + (size_t)s3 * D_C))[lane];
        a0.x += v0.x; a0.y += v0.y; a0.z += v0.z; a0.w += v0.w;
        a1.x += v1.x; a1.y += v1.y; a1.z += v1.z; a1.w += v1.w;
        a2.x += v2.x; a2.y += v2.y; a2.z += v2.z; a2.w += v2.w;
        a3.x += v3.x; a3.y += v3.y; a3.z += v3.z; a3.w += v3.w;
    }
    for (; e < e1; ++e) {
        int s0 = __ldg(g_esrc + e);
        float4 v0 = ((const float4*)(feat + (size_t)s0 * D_C))[lane];
        a0.x += v0.x; a0.y += v0.y; a0.z += v0.z; a0.w += v0.w;
    }
    a0.x += a1.x + a2.x + a3.x;
    a0.y += a1.y + a2.y + a3.y;
    a0.z += a1.z + a2.z + a3.z;
    a0.w += a1.w + a2.w + a3.w;
    float nrm = rsqrtf(fmaxf((float)(e1 - e0), 1.0f));
    a0.x *= nrm; a0.y *= nrm; a0.z *= nrm; a0.w *= nrm;

    uint32_t h0, h1, l0, l1;
    split2(a0.x, a0.y, h0, l0);
    split2(a0.z, a0.w, h1, l1);
    size_t o = (size_t)node * 64 + lane * 2;
    *(uint2*)(g_hi + o) = make_uint2(h0, h1);
    *(uint2*)(g_lo + o) = make_uint2(l0, l1);
}

// ---------------------------------------------------------------------------
// K7: HMMA GEMM on pre-split tiles
// ---------------------------------------------------------------------------
__device__ __forceinline__ void ldsm_x4(uint32_t addr, uint32_t& r0, uint32_t& r1,
                                        uint32_t& r2, uint32_t& r3) {
    asm volatile("ldmatrix.sync.aligned.m8n8.x4.shared.b16 {%0,%1,%2,%3}, [%4];"
                 : "=r"(r0), "=r"(r1), "=r"(r2), "=r"(r3) : "r"(addr));
}
__device__ __forceinline__ void mma16816(float& c0, float& c1, float& c2, float& c3,
                                         uint32_t a0, uint32_t a1, uint32_t a2, uint32_t a3,
                                         uint32_t b0, uint32_t b1) {
    asm volatile("mma.sync.aligned.m16n8k16.row.col.f32.bf16.bf16.f32 "
                 "{%0,%1,%2,%3}, {%4,%5,%6,%7}, {%8,%9}, {%0,%1,%2,%3};"
                 : "+f"(c0), "+f"(c1), "+f"(c2), "+f"(c3)
                 : "r"(a0), "r"(a1), "r"(a2), "r"(a3), "r"(b0), "r"(b1));
}

__global__ __launch_bounds__(TPB, 1) void gemm_kernel(const float* __restrict__ W,
                                                      const float* __restrict__ b,
                                                      float* __restrict__ out) {
    extern __shared__ __align__(16) __nv_bfloat16 sm[];
    __nv_bfloat16* Ahi = sm;
    __nv_bfloat16* Alo = Ahi + TILE_HALF;
    __nv_bfloat16* Bhi = Alo + TILE_HALF;
    __nv_bfloat16* Blo = Bhi + TILE_HALF;
    __shared__ float bs[D_C];

    const int tid  = threadIdx.x;
    const int wid  = tid >> 5;
    const int lane = tid & 31;
    const int base = blockIdx.x * TILE_M;

    if (tid < D_C) bs[tid] = b[tid];

    // Fill A (pre-split h, streamed) and B (W split here): 2048 groups each
    #pragma unroll
    for (int it = 0; it < 8; ++it) {
        int idx = tid + it * TPB;
        int row = idx >> 4;                // 0..127
        int kc  = (idx & 15) << 3;         // k base, 8 elems (= 4 words)
        int so  = row * RS + kc;
        int node = base + row;

        // A: direct uint4 copy from g_hi/g_lo
        if (node < N_NODES_C) {
            size_t go = (size_t)node * 64 + (kc >> 1);
            *(uint4*)(Ahi + so) = *(const uint4*)(g_hi + go);
            *(uint4*)(Alo + so) = *(const uint4*)(g_lo + go);
        } else {
            *(uint4*)(Ahi + so) = make_uint4(0, 0, 0, 0);
            *(uint4*)(Alo + so) = make_uint4(0, 0, 0, 0);
        }

        // B: split W
        const float4* wp = (const float4*)(W + (size_t)row * D_C + kc);
        float4 w0 = wp[0], w1 = wp[1];
        float v[8] = {w0.x, w0.y, w0.z, w0.w, w1.x, w1.y, w1.z, w1.w};
        uint32_t hi[4], lo[4];
        #pragma unroll
        for (int j = 0; j < 4; j++) split2(v[2*j], v[2*j+1], hi[j], lo[j]);
        *(uint4*)(Bhi + so) = make_uint4(hi[0], hi[1], hi[2], hi[3]);
        *(uint4*)(Blo + so) = make_uint4(lo[0], lo[1], lo[2], lo[3]);
    }
    __syncthreads();

    // HMMA mainloop: 4(M) x 2(N) warp tiling
    const int m0 = (wid & 3) * 32;
    const int n0 = (wid >> 2) * 64;

    float acc[2][8][4];
    #pragma unroll
    for (int f = 0; f < 2; f++)
        #pragma unroll
        for (int nb = 0; nb < 8; nb++)
            #pragma unroll
            for (int j = 0; j < 4; j++) acc[f][nb][j] = 0.f;

    uint32_t aBase[2];
    #pragma unroll
    for (int f = 0; f < 2; f++)
        aBase[f] = smem_u32(Ahi) +
                   (uint32_t)(((m0 + f * 16 + (lane & 15)) * RS + ((lane >> 4) << 3)) * 2);
    uint32_t bBase[4];
    #pragma unroll
    for (int p = 0; p < 4; p++)
        bBase[p] = smem_u32(Bhi) +
                   (uint32_t)(((n0 + 16 * p + (lane & 7) + ((lane >> 4) << 3)) * RS +
                               (((lane >> 3) & 1) << 3)) * 2);

    const uint32_t LO_D = (uint32_t)TILE_BYTES_SM;

    #pragma unroll
    for (int prod = 0; prod < 3; prod++) {
        uint32_t dA = (prod == 1) ? LO_D : 0u;
        uint32_t dB = (prod == 2) ? LO_D : 0u;
        #pragma unroll
        for (int kk = 0; kk < 8; kk++) {
            uint32_t koff = (uint32_t)(kk * 16 * 2);
            uint32_t a[2][4];
            #pragma unroll
            for (int f = 0; f < 2; f++)
                ldsm_x4(aBase[f] + dA + koff, a[f][0], a[f][1], a[f][2], a[f][3]);
            #pragma unroll
            for (int p = 0; p < 4; p++) {
                uint32_t b0, b1, b2, b3;
                ldsm_x4(bBase[p] + dB + koff, b0, b1, b2, b3);
                #pragma unroll
                for (int f = 0; f < 2; f++) {
                    mma16816(acc[f][2*p  ][0], acc[f][2*p  ][1], acc[f][2*p  ][2], acc[f][2*p  ][3],
                             a[f][0], a[f][1], a[f][2], a[f][3], b0, b1);
                    mma16816(acc[f][2*p+1][0], acc[f][2*p+1][1], acc[f][2*p+1][2], acc[f][2*p+1][3],
                             a[f][0], a[f][1], a[f][2], a[f][3], b2, b3);
                }
            }
        }
    }

    // epilogue
    const int qr = lane >> 2;
    const int qc = (lane & 3) * 2;
    #pragma unroll
    for (int f = 0; f < 2; f++) {
        int m_lo = m0 + f * 16 + qr;
        int m_hi = m_lo + 8;
        int node_lo = base + m_lo;
        int node_hi = base + m_hi;
        #pragma unroll
        for (int nb = 0; nb < 8; nb++) {
            int col = n0 + nb * 8 + qc;
            float b0v = bs[col], b1v = bs[col + 1];
            if (node_lo < N_NODES_C) {
                float2 o = make_float2(acc[f][nb][0] + b0v, acc[f][nb][1] + b1v);
                *(float2*)(out + (size_t)node_lo * D_C + col) = o;
            }
            if (node_hi < N_NODES_C) {
                float2 o = make_float2(acc[f][nb][2] + b0v, acc[f][nb][3] + b1v);
                *(float2*)(out + (size_t)node_hi * D_C + col) = o;
            }
        }
    }
}

// ---------------------------------------------------------------------------
// kernel_launch
// ---------------------------------------------------------------------------
extern "C" void kernel_launch(void* const* d_in, const int* in_sizes, int n_in,
                              void* d_out, int out_size) {
    const float* feat = (const float*)d_in[0];   // [100000,128] f32
    const int*   src  = (const int*)d_in[1];     // [600000] i32
    const int*   dst  = (const int*)d_in[2];     // [600000] i32
    const float* W    = (const float*)d_in[3];   // [128,128] f32
    const float* b    = (const float*)d_in[4];   // [128] f32
    float*       out  = (float*)d_out;

    const int n_edges = in_sizes[1];

    const int smem_bytes = 4 * TILE_BYTES_SM;    // 139264 B dynamic
    cudaFuncSetAttribute(gemm_kernel,
                         cudaFuncAttributeMaxDynamicSharedMemorySize, smem_bytes);

    // CSR build
    zero_deg_kernel<<<(N_NODES_C + TPB - 1) / TPB, TPB>>>();
    hist_kernel<<<(n_edges + TPB - 1) / TPB, TPB>>>(dst, n_edges);
    scan_a_kernel<<<NB_SCAN, SCAN_B>>>();
    scan_c_kernel<<<NB_SCAN, SCAN_B>>>(n_edges);
    permute_kernel<<<(n_edges + TPB - 1) / TPB, TPB>>>(src, dst, n_edges);

    // gather (high occupancy, warp per node) -> pre-split h
    gather_kernel<<<(N_NODES_C * 32 + TPB - 1) / TPB, TPB>>>(feat);

    // GEMM on pre-split tiles
    gemm_kernel<<<GEMM_GRID, TPB, smem_bytes>>>(W, b, out);
}